// round 2
// baseline (speedup 1.0000x reference)
#include <cuda_runtime.h>

#define B   128
#define H0  224
#define W0  224
#define C1  16
#define H1  112
#define W1  112
#define HP  56
#define WP  56
#define C2  32
#define H2  28
#define W2  28
#define BN_EPS 1e-5f

// ---------------- scratch (static device memory; no allocation) ----------------
__device__ float  g_y1[B * C1 * H1 * W1];   // conv1 raw output  (~103 MB)
__device__ float  g_h1[B * C1 * HP * WP];   // bn1+relu+maxpool  (~26 MB)
__device__ float  g_y2[B * C2 * H2 * W2];   // conv2 raw output  (~13 MB)
__device__ double g_sum1[C1], g_sq1[C1];
__device__ double g_sum2[C2], g_sq2[C2];
__device__ float  g_bnp1[2 * C1];           // [scale[16], shift[16]]
__device__ float  g_bnp2[2 * C2];           // [scale[32], shift[32]]

// ---------------- kernels ----------------
__global__ void k_zero() {
    int t = threadIdx.x;
    if (t < C1) { g_sum1[t] = 0.0; g_sq1[t] = 0.0; }
    if (t < C2) { g_sum2[t] = 0.0; g_sq2[t] = 0.0; }
}

// conv1: each thread computes 2 adjacent output pixels (wo, wo+1) for ALL 16
// output channels. Bias omitted (cancels exactly in training-mode BN).
__global__ void k_conv1(const float* __restrict__ x, const float* __restrict__ w) {
    __shared__ float ws[C1 * 27];
    for (int i = threadIdx.x; i < C1 * 27; i += blockDim.x) ws[i] = w[i];
    __syncthreads();

    int t   = blockIdx.x * blockDim.x + threadIdx.x;   // grid exactly covers tasks
    int wo2 = t % (W1 / 2);
    int ho  = (t / (W1 / 2)) % H1;
    int n   = t / ((W1 / 2) * H1);

    float a0[C1], a1[C1];
#pragma unroll
    for (int c = 0; c < C1; c++) { a0[c] = 0.f; a1[c] = 0.f; }

    const int cb = 4 * wo2 - 1;   // leftmost input col; only cb==-1 can be OOB
#pragma unroll
    for (int i = 0; i < 3; i++) {
#pragma unroll
        for (int ky = 0; ky < 3; ky++) {
            int r = 2 * ho - 1 + ky;
            if (r < 0 || r >= H0) continue;
            const float* xr = x + ((n * 3 + i) * H0 + r) * W0;
            float va[5];
            va[0] = (cb >= 0) ? __ldg(xr + cb) : 0.f;
            va[1] = __ldg(xr + cb + 1);
            va[2] = __ldg(xr + cb + 2);
            va[3] = __ldg(xr + cb + 3);
            va[4] = __ldg(xr + cb + 4);
#pragma unroll
            for (int kx = 0; kx < 3; kx++) {
                float p = va[kx], q = va[kx + 2];
#pragma unroll
                for (int c = 0; c < C1; c++) {
                    float wv = ws[c * 27 + i * 9 + ky * 3 + kx];
                    a0[c] = fmaf(wv, p, a0[c]);
                    a1[c] = fmaf(wv, q, a1[c]);
                }
            }
        }
    }
    int wo = 2 * wo2;
#pragma unroll
    for (int c = 0; c < C1; c++) {
        float2 st = make_float2(a0[c], a1[c]);
        *reinterpret_cast<float2*>(&g_y1[((n * C1 + c) * H1 + ho) * W1 + wo]) = st;
    }
}

// per-channel sum / sumsq over y1; one block per (n, c) slice
__global__ void k_stats1() {
    int blk = blockIdx.x;          // n*C1 + c
    int c   = blk % C1;
    const float* p = g_y1 + blk * (H1 * W1);
    float s = 0.f, q = 0.f;
    for (int i = threadIdx.x; i < H1 * W1; i += blockDim.x) {
        float v = p[i];
        s += v;
        q = fmaf(v, v, q);
    }
    __shared__ float ss[256], sq[256];
    ss[threadIdx.x] = s; sq[threadIdx.x] = q;
    __syncthreads();
    for (int o = 128; o > 0; o >>= 1) {
        if (threadIdx.x < o) {
            ss[threadIdx.x] += ss[threadIdx.x + o];
            sq[threadIdx.x] += sq[threadIdx.x + o];
        }
        __syncthreads();
    }
    if (threadIdx.x == 0) {
        atomicAdd(&g_sum1[c], (double)ss[0]);
        atomicAdd(&g_sq1[c], (double)sq[0]);
    }
}

__global__ void k_params1(const float* __restrict__ gamma, const float* __restrict__ beta) {
    int c = threadIdx.x;
    if (c < C1) {
        double cnt  = (double)B * H1 * W1;
        double mean = g_sum1[c] / cnt;
        double var  = g_sq1[c] / cnt - mean * mean;
        float scale = gamma[c] * (1.0f / sqrtf((float)var + BN_EPS));
        g_bnp1[c]      = scale;
        g_bnp1[C1 + c] = beta[c] - (float)mean * scale;
    }
}

// fused BN1 + ReLU + 2x2 maxpool
__global__ void k_pool() {
    int o = blockIdx.x * blockDim.x + threadIdx.x;
    const int total = B * C1 * HP * WP;
    if (o >= total) return;
    int j = o % WP;
    int i = (o / WP) % HP;
    int c = (o / (WP * HP)) % C1;
    int n = o / (WP * HP * C1);
    float scale = g_bnp1[c], shift = g_bnp1[C1 + c];
    const float* p = g_y1 + ((n * C1 + c) * H1 + 2 * i) * W1 + 2 * j;
    float e00 = fmaxf(fmaf(scale, p[0],      shift), 0.f);
    float e01 = fmaxf(fmaf(scale, p[1],      shift), 0.f);
    float e10 = fmaxf(fmaf(scale, p[W1],     shift), 0.f);
    float e11 = fmaxf(fmaf(scale, p[W1 + 1], shift), 0.f);
    g_h1[o] = fmaxf(fmaxf(e00, e01), fmaxf(e10, e11));
}

// conv2: each thread = one (n, ho, wo), all 32 output channels. Bias omitted (BN).
__global__ void k_conv2(const float* __restrict__ w) {
    __shared__ float ws[C2 * C1 * 9];   // 4608 floats
    for (int i = threadIdx.x; i < C2 * C1 * 9; i += blockDim.x) ws[i] = w[i];
    __syncthreads();

    int t = blockIdx.x * blockDim.x + threadIdx.x;
    const int total = B * H2 * W2;
    if (t >= total) return;
    int wo = t % W2;
    int ho = (t / W2) % H2;
    int n  = t / (W2 * H2);

    float acc[C2];
#pragma unroll
    for (int c = 0; c < C2; c++) acc[c] = 0.f;

    const int cb = 2 * wo - 1;   // only cb==-1 can be OOB (cb+2 <= 55 always)
    for (int i = 0; i < C1; i++) {
#pragma unroll
        for (int ky = 0; ky < 3; ky++) {
            int r = 2 * ho - 1 + ky;
            if (r < 0 || r >= HP) continue;
            const float* hr = g_h1 + ((n * C1 + i) * HP + r) * WP;
            float va[3];
            va[0] = (cb >= 0) ? hr[cb] : 0.f;
            va[1] = hr[cb + 1];
            va[2] = hr[cb + 2];
#pragma unroll
            for (int kx = 0; kx < 3; kx++) {
                float p = va[kx];
#pragma unroll
                for (int c = 0; c < C2; c++)
                    acc[c] = fmaf(ws[((c * C1 + i) * 3 + ky) * 3 + kx], p, acc[c]);
            }
        }
    }
#pragma unroll
    for (int c = 0; c < C2; c++)
        g_y2[((n * C2 + c) * H2 + ho) * W2 + wo] = acc[c];
}

__global__ void k_stats2() {
    int blk = blockIdx.x;          // n*C2 + c
    int c   = blk % C2;
    const float* p = g_y2 + blk * (H2 * W2);
    float s = 0.f, q = 0.f;
    for (int i = threadIdx.x; i < H2 * W2; i += blockDim.x) {
        float v = p[i];
        s += v;
        q = fmaf(v, v, q);
    }
    __shared__ float ss[256], sq[256];
    ss[threadIdx.x] = s; sq[threadIdx.x] = q;
    __syncthreads();
    for (int o = 128; o > 0; o >>= 1) {
        if (threadIdx.x < o) {
            ss[threadIdx.x] += ss[threadIdx.x + o];
            sq[threadIdx.x] += sq[threadIdx.x + o];
        }
        __syncthreads();
    }
    if (threadIdx.x == 0) {
        atomicAdd(&g_sum2[c], (double)ss[0]);
        atomicAdd(&g_sq2[c], (double)sq[0]);
    }
}

__global__ void k_params2(const float* __restrict__ gamma, const float* __restrict__ beta) {
    int c = threadIdx.x;
    if (c < C2) {
        double cnt  = (double)B * H2 * W2;
        double mean = g_sum2[c] / cnt;
        double var  = g_sq2[c] / cnt - mean * mean;
        float scale = gamma[c] * (1.0f / sqrtf((float)var + BN_EPS));
        g_bnp2[c]      = scale;
        g_bnp2[C2 + c] = beta[c] - (float)mean * scale;
    }
}

// BN2 + ReLU + global avg pool + fc + cos, one block per sample
__global__ void k_final(const float* __restrict__ fcw, const float* __restrict__ fcb,
                        float* __restrict__ out) {
    __shared__ float sw[C2], sscale[C2], sshift[C2];
    int tid = threadIdx.x;
    if (tid < C2) {
        sw[tid]     = fcw[tid];
        sscale[tid] = g_bnp2[tid];
        sshift[tid] = g_bnp2[C2 + tid];
    }
    __syncthreads();

    int n = blockIdx.x;
    const float* p = g_y2 + n * C2 * H2 * W2;
    float acc = 0.f;
    for (int idx = tid; idx < C2 * H2 * W2; idx += blockDim.x) {
        int c   = idx / (H2 * W2);
        float v = p[idx];
        float e = fmaxf(fmaf(sscale[c], v, sshift[c]), 0.f);
        acc = fmaf(sw[c], e, acc);
    }
    __shared__ float red[256];
    red[tid] = acc;
    __syncthreads();
    for (int o = 128; o > 0; o >>= 1) {
        if (tid < o) red[tid] += red[tid + o];
        __syncthreads();
    }
    if (tid == 0) {
        float logit = red[0] / (float)(H2 * W2) + fcb[0];
        float pr = cosf(logit);
        out[2 * n]     = pr;
        out[2 * n + 1] = 1.f - pr;
    }
}

// ---------------- launcher ----------------
extern "C" void kernel_launch(void* const* d_in, const int* in_sizes, int n_in,
                              void* d_out, int out_size) {
    const float* x    = (const float*)d_in[0];
    const float* c1w  = (const float*)d_in[1];
    // d_in[2] conv1_b: cancels in training-mode BN — unused
    const float* bn1g = (const float*)d_in[3];
    const float* bn1b = (const float*)d_in[4];
    const float* c2w  = (const float*)d_in[5];
    // d_in[6] conv2_b: cancels in training-mode BN — unused
    const float* bn2g = (const float*)d_in[7];
    const float* bn2b = (const float*)d_in[8];
    const float* fcw  = (const float*)d_in[9];
    const float* fcb  = (const float*)d_in[10];
    float* out = (float*)d_out;

    k_zero<<<1, 32>>>();
    k_conv1<<<(B * H1 * (W1 / 2)) / 256, 256>>>(x, c1w);           // 3136 blocks
    k_stats1<<<B * C1, 256>>>();
    k_params1<<<1, C1>>>(bn1g, bn1b);
    k_pool<<<(B * C1 * HP * WP + 255) / 256, 256>>>();
    k_conv2<<<(B * H2 * W2 + 255) / 256, 256>>>(c2w);
    k_stats2<<<B * C2, 256>>>();
    k_params2<<<1, C2>>>(bn2g, bn2b);
    k_final<<<B, 256>>>(fcw, fcb, out);
}

// round 3
// speedup vs baseline: 1.1348x; 1.1348x over previous
#include <cuda_runtime.h>
#include <cuda_fp16.h>

#define B   128
#define H0  224
#define W0  224
#define C1  16
#define HP  56          // pooled H/W after conv1(stride2) + maxpool2
#define C2  32
#define H2  28
#define W2  28
#define BN_EPS 1e-5f

#define NPIX1 ((double)B * 112.0 * 112.0)   // BN1 stats population (pre-pool y1)
#define NPIX2 ((double)B * H2 * W2)

// ---------------- scratch (static device memory) ----------------
__device__ __half  g_u1[B * C1 * HP * HP];     // maxpool(conv1) raw (pre-BN), fp16, ~13MB
__device__ __half  g_y2[B * C2 * H2 * W2];     // conv2 raw (pre-BN), fp16, ~6.4MB
__device__ double  g_part1[32][C1][2];         // binned (sum, sumsq) for BN1
__device__ double  g_part2[16][C2][2];         // binned (sum, sumsq) for BN2

// ---------------- f32x2 helpers (Blackwell dual-fp32) ----------------
__device__ __forceinline__ unsigned long long pk2(float lo, float hi) {
    unsigned long long r;
    asm("mov.b64 %0, {%1, %2};" : "=l"(r) : "f"(lo), "f"(hi));
    return r;
}
__device__ __forceinline__ void upk2(unsigned long long v, float& lo, float& hi) {
    asm("mov.b64 {%0, %1}, %2;" : "=f"(lo), "=f"(hi) : "l"(v));
}
#define FMA2(acc, a, b) asm("fma.rn.f32x2 %0, %1, %2, %0;" : "+l"(acc) : "l"(a), "l"(b))

// ---------------- kernels ----------------
__global__ void k_zero() {
    double* p1 = &g_part1[0][0][0];
    double* p2 = &g_part2[0][0][0];
    for (int i = threadIdx.x; i < 32 * C1 * 2; i += blockDim.x) p1[i] = 0.0;
    for (int i = threadIdx.x; i < 16 * C2 * 2; i += blockDim.x) p2[i] = 0.0;
}

// conv1 (stride2, pad1, bias cancels in BN) + in-register 2x2 maxpool + BN1 stats.
// One thread = one pooled output (n,i,j) = 2x2 block of y1 pixels, all 16 channels.
__global__ void __launch_bounds__(256) k_conv1pool(const float* __restrict__ x,
                                                   const float* __restrict__ w) {
    __shared__ unsigned long long ws2[C1 * 27];   // (w,w) duplicated pairs
    __shared__ float sh_s[C1], sh_q[C1];
    for (int idx = threadIdx.x; idx < C1 * 27; idx += blockDim.x) {
        int c = idx & 15, k27 = idx >> 4;
        float wv = w[c * 27 + k27];
        ws2[idx] = pk2(wv, wv);
    }
    if (threadIdx.x < C1) { sh_s[threadIdx.x] = 0.f; sh_q[threadIdx.x] = 0.f; }
    __syncthreads();

    int t = blockIdx.x * blockDim.x + threadIdx.x;   // exact grid: B*56*56
    int j = t % HP;
    int i = (t / HP) % HP;
    int n = t / (HP * HP);

    unsigned long long acc01[C1], acc23[C1];   // pixels (0,0),(0,1) | (1,0),(1,1)
#pragma unroll
    for (int c = 0; c < C1; c++) { acc01[c] = 0ull; acc23[c] = 0ull; }

    const int rb = 4 * i - 1;   // only -1 can be OOB (max 4*55+3 = 223)
    const int cb = 4 * j - 1;

    float patch[5][5];
#pragma unroll 1
    for (int ic = 0; ic < 3; ic++) {
        const float* base = x + ((n * 3 + ic) * H0) * W0;
#pragma unroll
        for (int r = 0; r < 5; r++) {
            int row = rb + r;
            if (row < 0) {
#pragma unroll
                for (int cc = 0; cc < 5; cc++) patch[r][cc] = 0.f;
            } else {
                const float* xr = base + row * W0;
                patch[r][0] = (cb >= 0) ? __ldg(xr + cb) : 0.f;
#pragma unroll
                for (int cc = 1; cc < 5; cc++) patch[r][cc] = __ldg(xr + cb + cc);
            }
        }
#pragma unroll
        for (int ky = 0; ky < 3; ky++) {
#pragma unroll
            for (int kx = 0; kx < 3; kx++) {
                unsigned long long v01 = pk2(patch[ky][kx],     patch[ky][kx + 2]);
                unsigned long long v23 = pk2(patch[ky + 2][kx], patch[ky + 2][kx + 2]);
                const unsigned long long* wrow = &ws2[(ic * 9 + ky * 3 + kx) * C1];
#pragma unroll
                for (int c = 0; c < C1; c++) {
                    unsigned long long wv = wrow[c];
                    FMA2(acc01[c], v01, wv);
                    FMA2(acc23[c], v23, wv);
                }
            }
        }
    }

    // write pooled max + reduce stats
    __half* up = g_u1 + ((n * C1) * HP + i) * HP + j;
#pragma unroll
    for (int c = 0; c < C1; c++) {
        float a0, a1, a2, a3;
        upk2(acc01[c], a0, a1);
        upk2(acc23[c], a2, a3);
        up[c * HP * HP] = __float2half(fmaxf(fmaxf(a0, a1), fmaxf(a2, a3)));
        float s = (a0 + a1) + (a2 + a3);
        float q = fmaf(a0, a0, fmaf(a1, a1, fmaf(a2, a2, a3 * a3)));
#pragma unroll
        for (int o = 16; o > 0; o >>= 1) {
            s += __shfl_xor_sync(0xffffffffu, s, o);
            q += __shfl_xor_sync(0xffffffffu, q, o);
        }
        if ((threadIdx.x & 31) == 0) {
            atomicAdd(&sh_s[c], s);
            atomicAdd(&sh_q[c], q);
        }
    }
    __syncthreads();
    if (threadIdx.x < C1) {
        int bin = blockIdx.x & 31;
        atomicAdd(&g_part1[bin][threadIdx.x][0], (double)sh_s[threadIdx.x]);
        atomicAdd(&g_part1[bin][threadIdx.x][1], (double)sh_q[threadIdx.x]);
    }
}

// conv2 (stride2, pad1) with inline BN1+ReLU on loads, fused BN2 stats.
// One thread = one output pixel (n,ho,wo), all 32 channels (paired for f32x2).
__global__ void __launch_bounds__(256) k_conv2(const float* __restrict__ w,
                                               const float* __restrict__ g1,
                                               const float* __restrict__ b1) {
    __shared__ unsigned long long ws2[16 * C1 * 9];   // [(i*9+q)][c2] (w_{2c2}, w_{2c2+1})
    __shared__ float sc1[C1], sh1[C1];
    __shared__ float s2s[C2], s2q[C2];
    for (int idx = threadIdx.x; idx < 16 * C1 * 9; idx += blockDim.x) {
        int c2 = idx & 15, k144 = idx >> 4;
        ws2[idx] = pk2(w[(2 * c2) * 144 + k144], w[(2 * c2 + 1) * 144 + k144]);
    }
    if (threadIdx.x < C1) {
        int c = threadIdx.x;
        double s = 0.0, q = 0.0;
#pragma unroll
        for (int bb = 0; bb < 32; bb++) { s += g_part1[bb][c][0]; q += g_part1[bb][c][1]; }
        double mean = s / NPIX1;
        double var  = q / NPIX1 - mean * mean;
        float scale = g1[c] * (1.0f / sqrtf((float)var + BN_EPS));
        sc1[c] = scale;
        sh1[c] = b1[c] - (float)mean * scale;
    }
    if (threadIdx.x < C2) { s2s[threadIdx.x] = 0.f; s2q[threadIdx.x] = 0.f; }
    __syncthreads();

    int t  = blockIdx.x * blockDim.x + threadIdx.x;   // exact grid: B*28*28
    int wo = t % W2;
    int ho = (t / W2) % H2;
    int n  = t / (W2 * H2);

    unsigned long long acc[16];
#pragma unroll
    for (int c2 = 0; c2 < 16; c2++) acc[c2] = 0ull;

    const int cb = 2 * wo - 1;   // only -1 can be OOB (max 2*27+1 = 55)
#pragma unroll 1
    for (int ic = 0; ic < C1; ic++) {
        float sc = sc1[ic], sh = sh1[ic];
        const __half* base = g_u1 + ((n * C1 + ic) * HP) * HP;
#pragma unroll
        for (int ky = 0; ky < 3; ky++) {
            int row = 2 * ho - 1 + ky;
            if (row < 0) continue;                   // max row = 55, always < HP
            const __half* hr = base + row * HP;
            unsigned long long vv[3];
#pragma unroll
            for (int kx = 0; kx < 3; kx++) {
                int col = cb + kx;
                float h = 0.f;
                if (col >= 0) {
                    float v = __half2float(hr[col]);
                    h = fmaxf(fmaf(sc, v, sh), 0.f);   // BN1 + ReLU (zero-pad stays 0)
                }
                vv[kx] = pk2(h, h);
            }
            const unsigned long long* wrow = &ws2[(ic * 9 + ky * 3) * 16];
#pragma unroll
            for (int kx = 0; kx < 3; kx++) {
#pragma unroll
                for (int c2 = 0; c2 < 16; c2++)
                    FMA2(acc[c2], vv[kx], wrow[kx * 16 + c2]);
            }
        }
    }

    // write y2 + BN2 stats
    __half* yp = g_y2 + ((n * C2) * H2 + ho) * W2 + wo;
#pragma unroll
    for (int c2 = 0; c2 < 16; c2++) {
        float f0, f1;
        upk2(acc[c2], f0, f1);
        yp[(2 * c2) * H2 * W2]     = __float2half(f0);
        yp[(2 * c2 + 1) * H2 * W2] = __float2half(f1);
        float s0 = f0, q0 = f0 * f0, s1 = f1, q1 = f1 * f1;
#pragma unroll
        for (int o = 16; o > 0; o >>= 1) {
            s0 += __shfl_xor_sync(0xffffffffu, s0, o);
            q0 += __shfl_xor_sync(0xffffffffu, q0, o);
            s1 += __shfl_xor_sync(0xffffffffu, s1, o);
            q1 += __shfl_xor_sync(0xffffffffu, q1, o);
        }
        if ((threadIdx.x & 31) == 0) {
            atomicAdd(&s2s[2 * c2], s0);     atomicAdd(&s2q[2 * c2], q0);
            atomicAdd(&s2s[2 * c2 + 1], s1); atomicAdd(&s2q[2 * c2 + 1], q1);
        }
    }
    __syncthreads();
    if (threadIdx.x < C2) {
        int bin = blockIdx.x & 15;
        atomicAdd(&g_part2[bin][threadIdx.x][0], (double)s2s[threadIdx.x]);
        atomicAdd(&g_part2[bin][threadIdx.x][1], (double)s2q[threadIdx.x]);
    }
}

// BN2 + ReLU + global avg + fc + cos; one block per sample
__global__ void k_final(const float* __restrict__ g2, const float* __restrict__ b2,
                        const float* __restrict__ fcw, const float* __restrict__ fcb,
                        float* __restrict__ out) {
    __shared__ float sw[C2], ssc[C2], ssh[C2];
    __shared__ float red[256];
    int tid = threadIdx.x;
    if (tid < C2) {
        double s = 0.0, q = 0.0;
#pragma unroll
        for (int bb = 0; bb < 16; bb++) { s += g_part2[bb][tid][0]; q += g_part2[bb][tid][1]; }
        double mean = s / NPIX2;
        double var  = q / NPIX2 - mean * mean;
        float scale = g2[tid] * (1.0f / sqrtf((float)var + BN_EPS));
        ssc[tid] = scale;
        ssh[tid] = b2[tid] - (float)mean * scale;
        sw[tid]  = fcw[tid];
    }
    __syncthreads();

    int n = blockIdx.x;
    const __half* p = g_y2 + n * C2 * H2 * W2;
    float acc = 0.f;
#pragma unroll 1
    for (int c = 0; c < C2; c++) {
        float fw = sw[c], sc = ssc[c], sh = ssh[c];
        const __half* pc = p + c * H2 * W2;
        for (int i = tid; i < H2 * W2; i += 256) {
            float e = fmaxf(fmaf(sc, __half2float(pc[i]), sh), 0.f);
            acc = fmaf(fw, e, acc);
        }
    }
    red[tid] = acc;
    __syncthreads();
    for (int o = 128; o > 0; o >>= 1) {
        if (tid < o) red[tid] += red[tid + o];
        __syncthreads();
    }
    if (tid == 0) {
        float logit = red[0] / (float)(H2 * W2) + fcb[0];
        float pr = cosf(logit);
        out[2 * n]     = pr;
        out[2 * n + 1] = 1.f - pr;
    }
}

// ---------------- launcher ----------------
extern "C" void kernel_launch(void* const* d_in, const int* in_sizes, int n_in,
                              void* d_out, int out_size) {
    const float* x    = (const float*)d_in[0];
    const float* c1w  = (const float*)d_in[1];
    // d_in[2] conv1_b cancels in training-mode BN
    const float* bn1g = (const float*)d_in[3];
    const float* bn1b = (const float*)d_in[4];
    const float* c2w  = (const float*)d_in[5];
    // d_in[6] conv2_b cancels in training-mode BN
    const float* bn2g = (const float*)d_in[7];
    const float* bn2b = (const float*)d_in[8];
    const float* fcw  = (const float*)d_in[9];
    const float* fcb  = (const float*)d_in[10];
    float* out = (float*)d_out;

    k_zero<<<1, 256>>>();
    k_conv1pool<<<(B * HP * HP) / 256, 256>>>(x, c1w);     // 1568 blocks
    k_conv2<<<(B * H2 * W2) / 256, 256>>>(c2w, bn1g, bn1b); // 392 blocks
    k_final<<<B, 256>>>(bn2g, bn2b, fcw, fcb, out);
}

// round 4
// speedup vs baseline: 1.3696x; 1.2070x over previous
#include <cuda_runtime.h>
#include <cuda_fp16.h>

#define B   128
#define H0  224
#define W0  224
#define C1  16
#define HP  56          // pooled H/W after conv1(stride2) + maxpool2
#define C2  32
#define H2  28
#define W2  28
#define BN_EPS 1e-5f

#define NPIX1 ((double)B * 112.0 * 112.0)   // BN1 population (pre-pool y1)
#define NPIX2 ((double)B * H2 * W2)

// ---------------- scratch (static device memory) ----------------
__device__ __half  g_u1[B * HP * HP * C1];     // NHWC maxpool(conv1) raw, fp16 (~13MB)
__device__ __half  g_y2[B * H2 * W2 * C2];     // NHWC conv2 raw, fp16 (~6.4MB)
__device__ double  g_part1[32][C1][2];         // binned (sum, sumsq) for BN1
__device__ double  g_part2[16][C2][2];         // binned (sum, sumsq) for BN2

// ---------------- f32x2 helpers (Blackwell dual-fp32) ----------------
__device__ __forceinline__ unsigned long long pk2(float lo, float hi) {
    unsigned long long r;
    asm("mov.b64 %0, {%1, %2};" : "=l"(r) : "f"(lo), "f"(hi));
    return r;
}
__device__ __forceinline__ void upk2(unsigned long long v, float& lo, float& hi) {
    asm("mov.b64 {%0, %1}, %2;" : "=f"(lo), "=f"(hi) : "l"(v));
}
#define FMA2(acc, a, b) asm("fma.rn.f32x2 %0, %1, %2, %0;" : "+l"(acc) : "l"(a), "l"(b))

__device__ __forceinline__ void u4_to_f8(uint4 u, float* f) {
    float2 a;
    a = __half22float2(*reinterpret_cast<__half2*>(&u.x)); f[0] = a.x; f[1] = a.y;
    a = __half22float2(*reinterpret_cast<__half2*>(&u.y)); f[2] = a.x; f[3] = a.y;
    a = __half22float2(*reinterpret_cast<__half2*>(&u.z)); f[4] = a.x; f[5] = a.y;
    a = __half22float2(*reinterpret_cast<__half2*>(&u.w)); f[6] = a.x; f[7] = a.y;
}

// ---------------- kernels ----------------
__global__ void k_zero() {
    double* p1 = &g_part1[0][0][0];
    double* p2 = &g_part2[0][0][0];
    for (int i = threadIdx.x; i < 32 * C1 * 2; i += blockDim.x) p1[i] = 0.0;
    for (int i = threadIdx.x; i < 16 * C2 * 2; i += blockDim.x) p2[i] = 0.0;
}

// conv1 (stride2, pad1; bias cancels in BN) + in-register 2x2 maxpool + BN1 stats.
// One thread = one pooled output (n,i,j) for all 16 channels; NHWC output.
__global__ void __launch_bounds__(256) k_conv1pool(const float* __restrict__ x,
                                                   const float* __restrict__ w) {
    __shared__ unsigned long long ws2[27 * C1];   // [k27][c] duplicated (w,w) pairs
    __shared__ float sh_s[C1], sh_q[C1];
    for (int idx = threadIdx.x; idx < 27 * C1; idx += blockDim.x) {
        int c = idx & 15, k27 = idx >> 4;
        float wv = w[c * 27 + k27];
        ws2[idx] = pk2(wv, wv);
    }
    if (threadIdx.x < C1) { sh_s[threadIdx.x] = 0.f; sh_q[threadIdx.x] = 0.f; }
    __syncthreads();

    int t = blockIdx.x * blockDim.x + threadIdx.x;   // exact grid: B*56*56
    int j = t % HP;
    int i = (t / HP) % HP;
    int n = t / (HP * HP);

    unsigned long long acc01[C1], acc23[C1];   // pixels (r0,c0),(r0,c1) | (r1,c0),(r1,c1)
#pragma unroll
    for (int c = 0; c < C1; c++) { acc01[c] = 0ull; acc23[c] = 0ull; }

    const int rb = 4 * i - 1;   // only -1 can be OOB (max 4*55+3 = 223)
    const int cb = 4 * j - 1;

    float patch[5][5];
#pragma unroll 1
    for (int ic = 0; ic < 3; ic++) {
        const float* base = x + ((n * 3 + ic) * H0) * W0;
#pragma unroll
        for (int r = 0; r < 5; r++) {
            int row = rb + r;
            if (row < 0) {
#pragma unroll
                for (int cc = 0; cc < 5; cc++) patch[r][cc] = 0.f;
            } else {
                const float* xr = base + row * W0;
                patch[r][0] = (cb >= 0) ? __ldg(xr + cb) : 0.f;
                float4 v4 = *reinterpret_cast<const float4*>(xr + cb + 1);  // 16B-aligned
                patch[r][1] = v4.x; patch[r][2] = v4.y;
                patch[r][3] = v4.z; patch[r][4] = v4.w;
            }
        }
#pragma unroll
        for (int ky = 0; ky < 3; ky++) {
#pragma unroll
            for (int kx = 0; kx < 3; kx++) {
                unsigned long long v01 = pk2(patch[ky][kx],     patch[ky][kx + 2]);
                unsigned long long v23 = pk2(patch[ky + 2][kx], patch[ky + 2][kx + 2]);
                const unsigned long long* wrow = &ws2[(ic * 9 + ky * 3 + kx) * C1];
#pragma unroll
                for (int c = 0; c < C1; c++) {
                    unsigned long long wv = wrow[c];
                    FMA2(acc01[c], v01, wv);
                    FMA2(acc23[c], v23, wv);
                }
            }
        }
    }

    // pooled max -> NHWC store (16 halves = 32B contiguous) + BN1 stats
    __half hmax[C1];
#pragma unroll
    for (int c = 0; c < C1; c++) {
        float a0, a1, a2, a3;
        upk2(acc01[c], a0, a1);
        upk2(acc23[c], a2, a3);
        hmax[c] = __float2half(fmaxf(fmaxf(a0, a1), fmaxf(a2, a3)));
        float s = (a0 + a1) + (a2 + a3);
        float q = fmaf(a0, a0, fmaf(a1, a1, fmaf(a2, a2, a3 * a3)));
#pragma unroll
        for (int o = 16; o > 0; o >>= 1) {
            s += __shfl_xor_sync(0xffffffffu, s, o);
            q += __shfl_xor_sync(0xffffffffu, q, o);
        }
        if ((threadIdx.x & 31) == 0) {
            atomicAdd(&sh_s[c], s);
            atomicAdd(&sh_q[c], q);
        }
    }
    uint4* up = reinterpret_cast<uint4*>(g_u1 + ((n * HP + i) * HP + j) * C1);
    up[0] = *reinterpret_cast<uint4*>(&hmax[0]);
    up[1] = *reinterpret_cast<uint4*>(&hmax[8]);

    __syncthreads();
    if (threadIdx.x < C1) {
        int bin = blockIdx.x & 31;
        atomicAdd(&g_part1[bin][threadIdx.x][0], (double)sh_s[threadIdx.x]);
        atomicAdd(&g_part1[bin][threadIdx.x][1], (double)sh_q[threadIdx.x]);
    }
}

// conv2 (stride2, pad1) with inline BN1+ReLU on NHWC loads, fused BN2 stats.
// One thread = one output pixel (n,ho,wo), all 32 channels (paired for f32x2).
__global__ void __launch_bounds__(256) k_conv2(const float* __restrict__ w,
                                               const float* __restrict__ g1,
                                               const float* __restrict__ b1) {
    __shared__ unsigned long long ws2[9 * C1 * 16];   // [tap][ic][c2pair] (w_{2c},w_{2c+1})
    __shared__ float sc1[C1], sh1[C1];
    __shared__ float s2s[C2], s2q[C2];
    for (int idx = threadIdx.x; idx < 9 * C1 * 16; idx += blockDim.x) {
        int c2p = idx & 15;
        int ic  = (idx >> 4) & 15;
        int q   = idx >> 8;                            // 0..8 = ky*3+kx
        ws2[idx] = pk2(w[(2 * c2p) * 144 + ic * 9 + q],
                       w[(2 * c2p + 1) * 144 + ic * 9 + q]);
    }
    if (threadIdx.x < C1) {
        int c = threadIdx.x;
        double s = 0.0, q = 0.0;
#pragma unroll
        for (int bb = 0; bb < 32; bb++) { s += g_part1[bb][c][0]; q += g_part1[bb][c][1]; }
        double mean = s / NPIX1;
        double var  = q / NPIX1 - mean * mean;
        float scale = g1[c] * (1.0f / sqrtf((float)var + BN_EPS));
        sc1[c] = scale;
        sh1[c] = b1[c] - (float)mean * scale;
    }
    if (threadIdx.x < C2) { s2s[threadIdx.x] = 0.f; s2q[threadIdx.x] = 0.f; }
    __syncthreads();

    int t  = blockIdx.x * blockDim.x + threadIdx.x;   // exact grid: B*28*28
    int wo = t % W2;
    int ho = (t / W2) % H2;
    int n  = t / (W2 * H2);

    unsigned long long acc[16];
#pragma unroll
    for (int c2 = 0; c2 < 16; c2++) acc[c2] = 0ull;

#pragma unroll
    for (int ky = 0; ky < 3; ky++) {
        int row = 2 * ho - 1 + ky;
        bool rok = (row >= 0);                         // max row = 55 < HP always
#pragma unroll
        for (int kx = 0; kx < 3; kx++) {
            int col = 2 * wo - 1 + kx;
            unsigned long long vv[C1];
            if (rok && col >= 0) {
                const uint4* p = reinterpret_cast<const uint4*>(
                    g_u1 + ((n * HP + row) * HP + col) * C1);
                float f[16];
                u4_to_f8(p[0], f);
                u4_to_f8(p[1], f + 8);
#pragma unroll
                for (int ic = 0; ic < C1; ic++) {
                    float h = fmaxf(fmaf(sc1[ic], f[ic], sh1[ic]), 0.f);  // BN1+ReLU
                    vv[ic] = pk2(h, h);
                }
            } else {
#pragma unroll
                for (int ic = 0; ic < C1; ic++) vv[ic] = 0ull;            // zero padding
            }
            const unsigned long long* wq = &ws2[(ky * 3 + kx) * C1 * 16];
#pragma unroll
            for (int ic = 0; ic < C1; ic++) {
#pragma unroll
                for (int c2 = 0; c2 < 16; c2++)
                    FMA2(acc[c2], vv[ic], wq[ic * 16 + c2]);
            }
        }
    }

    // NHWC store (32 halves = 64B contiguous) + BN2 stats
    __half hout[C2];
#pragma unroll
    for (int c2 = 0; c2 < 16; c2++) {
        float f0, f1;
        upk2(acc[c2], f0, f1);
        hout[2 * c2]     = __float2half(f0);
        hout[2 * c2 + 1] = __float2half(f1);
        float s0 = f0, q0 = f0 * f0, s1 = f1, q1 = f1 * f1;
#pragma unroll
        for (int o = 16; o > 0; o >>= 1) {
            s0 += __shfl_xor_sync(0xffffffffu, s0, o);
            q0 += __shfl_xor_sync(0xffffffffu, q0, o);
            s1 += __shfl_xor_sync(0xffffffffu, s1, o);
            q1 += __shfl_xor_sync(0xffffffffu, q1, o);
        }
        if ((threadIdx.x & 31) == 0) {
            atomicAdd(&s2s[2 * c2], s0);     atomicAdd(&s2q[2 * c2], q0);
            atomicAdd(&s2s[2 * c2 + 1], s1); atomicAdd(&s2q[2 * c2 + 1], q1);
        }
    }
    uint4* yp = reinterpret_cast<uint4*>(g_y2 + ((n * H2 + ho) * W2 + wo) * C2);
#pragma unroll
    for (int k = 0; k < 4; k++) yp[k] = *reinterpret_cast<uint4*>(&hout[8 * k]);

    __syncthreads();
    if (threadIdx.x < C2) {
        int bin = blockIdx.x & 15;
        atomicAdd(&g_part2[bin][threadIdx.x][0], (double)s2s[threadIdx.x]);
        atomicAdd(&g_part2[bin][threadIdx.x][1], (double)s2q[threadIdx.x]);
    }
}

// BN2 + ReLU + global avg + fc + cos; one block per sample, uint4 NHWC loads.
__global__ void __launch_bounds__(256) k_final(const float* __restrict__ g2,
                                               const float* __restrict__ b2,
                                               const float* __restrict__ fcw,
                                               const float* __restrict__ fcb,
                                               float* __restrict__ out) {
    __shared__ float ssc[C2], ssh[C2], sw[C2];
    __shared__ float red[256];
    int tid = threadIdx.x;
    if (tid < C2) {
        double s = 0.0, q = 0.0;
#pragma unroll
        for (int bb = 0; bb < 16; bb++) { s += g_part2[bb][tid][0]; q += g_part2[bb][tid][1]; }
        double mean = s / NPIX2;
        double var  = q / NPIX2 - mean * mean;
        float scale = g2[tid] * (1.0f / sqrtf((float)var + BN_EPS));
        ssc[tid] = scale;
        ssh[tid] = b2[tid] - (float)mean * scale;
        sw[tid]  = fcw[tid];
    }
    __syncthreads();

    // channel group for this thread is loop-invariant: (idx & 3) == (tid & 3)
    int cg = (tid & 3) * 8;
    float rsc[8], rsh[8], rw[8];
#pragma unroll
    for (int k = 0; k < 8; k++) { rsc[k] = ssc[cg + k]; rsh[k] = ssh[cg + k]; rw[k] = sw[cg + k]; }

    int n = blockIdx.x;
    const uint4* p = reinterpret_cast<const uint4*>(g_y2 + n * H2 * W2 * C2);
    const int NV = H2 * W2 * C2 / 8;   // 3136 uint4 per sample
    float acc = 0.f;
    for (int i = tid; i < NV; i += 256) {
        float f[8];
        u4_to_f8(p[i], f);
#pragma unroll
        for (int k = 0; k < 8; k++) {
            float e = fmaxf(fmaf(rsc[k], f[k], rsh[k]), 0.f);
            acc = fmaf(rw[k], e, acc);
        }
    }
    red[tid] = acc;
    __syncthreads();
    for (int o = 128; o > 0; o >>= 1) {
        if (tid < o) red[tid] += red[tid + o];
        __syncthreads();
    }
    if (tid == 0) {
        float logit = red[0] / (float)(H2 * W2) + fcb[0];
        float pr = cosf(logit);
        out[2 * n]     = pr;
        out[2 * n + 1] = 1.f - pr;
    }
}

// ---------------- launcher ----------------
extern "C" void kernel_launch(void* const* d_in, const int* in_sizes, int n_in,
                              void* d_out, int out_size) {
    const float* x    = (const float*)d_in[0];
    const float* c1w  = (const float*)d_in[1];
    // d_in[2] conv1_b cancels in training-mode BN
    const float* bn1g = (const float*)d_in[3];
    const float* bn1b = (const float*)d_in[4];
    const float* c2w  = (const float*)d_in[5];
    // d_in[6] conv2_b cancels in training-mode BN
    const float* bn2g = (const float*)d_in[7];
    const float* bn2b = (const float*)d_in[8];
    const float* fcw  = (const float*)d_in[9];
    const float* fcb  = (const float*)d_in[10];
    float* out = (float*)d_out;

    k_zero<<<1, 256>>>();
    k_conv1pool<<<(B * HP * HP) / 256, 256>>>(x, c1w);      // 1568 blocks
    k_conv2<<<(B * H2 * W2) / 256, 256>>>(c2w, bn1g, bn1b); // 392 blocks
    k_final<<<B, 256>>>(bn2g, bn2b, fcw, fcb, out);
}